// round 9
// baseline (speedup 1.0000x reference)
#include <cuda_runtime.h>
#include <cstdint>

#define TSTEPS 2048
#define BATCH  32
#define EDIM   512
#define HDIM   512
#define C4     2048
#define NCTA   128

typedef unsigned long long ull;

__device__ float    g_xp[(size_t)TSTEPS * C4 * BATCH];   // [t][c][b]
__device__ float    g_embT[(size_t)TSTEPS * EDIM * BATCH]; // [t][k][b]
__device__ float    g_h[2][HDIM * BATCH];                // [col][b]
__device__ unsigned g_grp[8];
__device__ unsigned g_root;

__device__ __forceinline__ ull ffma2(ull a, ull b, ull c) {
    ull d;
    asm("fma.rn.f32x2 %0, %1, %2, %3;" : "=l"(d) : "l"(a), "l"(b), "l"(c));
    return d;
}
__device__ __forceinline__ ull fadd2(ull a, ull b) {
    ull d;
    asm("add.rn.f32x2 %0, %1, %2;" : "=l"(d) : "l"(a), "l"(b));
    return d;
}
__device__ __forceinline__ ull pack2(float lo, float hi) {
    return ((ull)__float_as_uint(hi) << 32) | (ull)__float_as_uint(lo);
}
__device__ __forceinline__ float sigf(float x) { return 1.0f / (1.0f + __expf(-x)); }
__device__ __forceinline__ float tanhf_fast(float x) {
    return __fmaf_rn(2.0f, sigf(2.0f * x), -1.0f);
}

// ---------------------------------------------------------------------------
__global__ void k_init() {
    int i = blockIdx.x * blockDim.x + threadIdx.x;
    if (i < 2 * HDIM * BATCH) ((float*)g_h)[i] = 0.0f;
    if (i < 8) g_grp[i] = 0u;
    if (i == 8) g_root = 0u;
}

// ---------------------------------------------------------------------------
// Transpose emb[t][b][k] -> g_embT[t][k][b]. One CTA per t.
// ---------------------------------------------------------------------------
__global__ void __launch_bounds__(256) k_transp(const float* __restrict__ emb) {
    extern __shared__ float tile[];       // [32 b][516] padded
    const int tid = threadIdx.x;
    const int t   = blockIdx.x;
    const float4* src = (const float4*)(emb + (size_t)t * (BATCH * EDIM));
    #pragma unroll
    for (int j = 0; j < 16; j++) {
        int fidx = j * 256 + tid;        // float4 index over [b][kq]
        int b  = fidx >> 7;
        int kq = fidx & 127;
        float4 v = src[b * 128 + kq];
        *(float4*)&tile[b * 516 + kq * 4] = v;
    }
    __syncthreads();
    float* dst = g_embT + (size_t)t * (EDIM * BATCH);
    #pragma unroll
    for (int j = 0; j < 16; j++) {
        int oidx = j * 256 + tid;        // over [k][bq]
        int k  = oidx >> 3;
        int bq = oidx & 7;
        float4 v;
        v.x = tile[(bq * 4 + 0) * 516 + k];
        v.y = tile[(bq * 4 + 1) * 516 + k];
        v.z = tile[(bq * 4 + 2) * 516 + k];
        v.w = tile[(bq * 4 + 3) * 516 + k];
        *(float4*)&dst[k * 32 + bq * 4] = v;
    }
}

// ---------------------------------------------------------------------------
// Phase 1: xp[t][c][b] = sum_k embT[t][k][b] * Wx[k][c] + bias[c]
// Outer-product microkernel: warp = 32b x 16c, thread = 4b x 4c.
// A via coalesced LDG.128 (L1 reuse across 8 warps); W dup'd in smem,
// 16 double-buffered 32-k chunks.
// ---------------------------------------------------------------------------
__global__ void __launch_bounds__(256, 2) k_xproj(
    const float* __restrict__ wxi, const float* __restrict__ wxf,
    const float* __restrict__ wxg, const float* __restrict__ wxo,
    const float* __restrict__ bi,  const float* __restrict__ bf,
    const float* __restrict__ bg,  const float* __restrict__ bo)
{
    extern __shared__ ull sx[];          // 2 bufs x [32 k][130] dup'd ull

    const int tid  = threadIdx.x;
    const int lane = tid & 31;
    const int wrp  = tid >> 5;
    const int t    = blockIdx.y;
    const int ct   = blockIdx.x;
    const int gate = ct >> 2;
    const int co   = (ct & 3) * 128;

    const float* W  = (gate == 0) ? wxi : (gate == 1) ? wxf : (gate == 2) ? wxg : wxo;
    const float* bs = (gate == 0) ? bi  : (gate == 1) ? bf  : (gate == 2) ? bg  : bo;

    const int b_grp = lane >> 2;         // 0..7 -> b = b_grp*4..+3
    const int c_grp = lane & 3;          // 0..3 -> c = wrp*16 + c_grp*4..+3

    float4 pre[4];
    auto load_chunk = [&](int kc) {
        #pragma unroll
        for (int j = 0; j < 4; j++) {
            int idx = j * 256 + tid;
            int kk  = (idx & 7) | ((idx >> 8) << 3);   // 0..31 in-warp k varies
            int c4  = (idx >> 3) & 31;
            pre[j] = *(const float4*)&W[(size_t)(kc * 32 + kk) * HDIM + co + c4 * 4];
        }
    };
    auto store_chunk = [&](ull* buf) {
        #pragma unroll
        for (int j = 0; j < 4; j++) {
            int idx = j * 256 + tid;
            int kk  = (idx & 7) | ((idx >> 8) << 3);
            int c4  = (idx >> 3) & 31;
            ull* d = buf + kk * 130 + c4 * 4;
            *(ulonglong2*)d       = make_ulonglong2(pack2(pre[j].x, pre[j].x),
                                                    pack2(pre[j].y, pre[j].y));
            *(ulonglong2*)(d + 2) = make_ulonglong2(pack2(pre[j].z, pre[j].z),
                                                    pack2(pre[j].w, pre[j].w));
        }
    };

    const float* At = g_embT + (size_t)t * (EDIM * BATCH);

    ull acc[8];
    #pragma unroll
    for (int j = 0; j < 8; j++) acc[j] = 0ull;

    load_chunk(0);
    store_chunk(sx);
    __syncthreads();

    int p = 0;
    for (int kc = 0; kc < 16; kc++) {
        if (kc < 15) load_chunk(kc + 1);
        const ull*   wb = sx + p * 4160;
        const float* Ab = At + (size_t)(kc * 32) * 32 + b_grp * 4;
        #pragma unroll 8
        for (int k = 0; k < 32; k++) {
            ull a0, a1;
            asm("ld.global.nc.v2.u64 {%0,%1}, [%2];"
                : "=l"(a0), "=l"(a1) : "l"(Ab + k * 32));
            const ull* wp = wb + k * 130 + wrp * 16 + c_grp * 4;
            ulonglong2 w01 = *(const ulonglong2*)wp;
            ulonglong2 w23 = *(const ulonglong2*)(wp + 2);
            acc[0] = ffma2(a0, w01.x, acc[0]);
            acc[1] = ffma2(a1, w01.x, acc[1]);
            acc[2] = ffma2(a0, w01.y, acc[2]);
            acc[3] = ffma2(a1, w01.y, acc[3]);
            acc[4] = ffma2(a0, w23.x, acc[4]);
            acc[5] = ffma2(a1, w23.x, acc[5]);
            acc[6] = ffma2(a0, w23.y, acc[6]);
            acc[7] = ffma2(a1, w23.y, acc[7]);
        }
        if (kc < 15) store_chunk(sx + (p ^ 1) * 4160);
        __syncthreads();
        p ^= 1;
    }

    // Epilogue: add bias, store xp[c][b] (coalesced STG.128).
    float* xp = g_xp + ((size_t)t * C4 + (size_t)gate * 512 + co) * 32;
    #pragma unroll
    for (int j = 0; j < 4; j++) {
        int c = wrp * 16 + c_grp * 4 + j;
        float bv = __ldg(&bs[co + c]);
        ull bd = pack2(bv, bv);
        ulonglong2 o;
        o.x = fadd2(acc[j * 2],     bd);
        o.y = fadd2(acc[j * 2 + 1], bd);
        *(ulonglong2*)&xp[(size_t)c * 32 + b_grp * 4] = o;
    }
}

// ---------------------------------------------------------------------------
// Phase 2: persistent recurrence. 128 CTAs x 512 threads; warp w owns
// k-slice [w*32, w*32+32) and the full 32b x 16c tile; same outer-product
// microkernel; packed f32x2 reduce; coalesced direct h stores; tree barrier.
// ---------------------------------------------------------------------------
__global__ void __launch_bounds__(512, 1) k_rec(
    const float* __restrict__ whi, const float* __restrict__ whf,
    const float* __restrict__ whg, const float* __restrict__ who,
    float* __restrict__ out)
{
    extern __shared__ ull sr[];
    ull*   whs = sr;                     // [512 k][16 lc] dup'd      (8192 ull)
    ull*   red = sr + 8192;              // [16 w][16 c x 18]         (4608 ull)
    ull*   sgu = sr + 12800;             // [16 c][16 bp]             (256 ull)
    float* sgf = (float*)sgu;
    float* ost = (float*)(sr + 13056);   // [32 b][4 hu]              (64 ull)

    const int tid  = threadIdx.x;
    const int lane = tid & 31;
    const int wrp  = tid >> 5;           // 0..15
    const int cta  = blockIdx.x;

    // Stage Wh dup'd: whs[k*16 + lc] = (w, w), col = cta*4 + (lc&3).
    for (int i = tid; i < 8192; i += 512) {
        int k = i >> 4, lc = i & 15;
        int g = lc >> 2, hu = lc & 3;
        const float* Wp = (g == 0) ? whi : (g == 1) ? whf : (g == 2) ? whg : who;
        float w = Wp[(size_t)k * HDIM + cta * 4 + hu];
        whs[i] = pack2(w, w);
    }
    __syncthreads();

    const int b_grp = lane >> 2;
    const int c_grp = lane & 3;
    const int k0    = wrp * 32;
    const int hu_g  = tid >> 5;          // gate phase (tid<128)
    const int b_g   = tid & 31;
    const int cl_r  = tid >> 4;          // reduce phase (tid<256)
    const int bp_r  = tid & 15;
    float c_state = 0.0f;

    unsigned* grpp  = &g_grp[cta >> 4];
    unsigned* rootp = &g_root;

    for (int t = 0; t < TSTEPS; t++) {
        const int pin = t & 1;
        const float* hin = g_h[pin];

        ull acc[8];
        #pragma unroll
        for (int j = 0; j < 8; j++) acc[j] = 0ull;

        const float* hb = hin + k0 * 32 + b_grp * 4;
        #pragma unroll 8
        for (int k = 0; k < 32; k++) {
            ull a0, a1;
            asm("ld.global.cg.v2.u64 {%0,%1}, [%2];"
                : "=l"(a0), "=l"(a1) : "l"(hb + k * 32));
            const ull* wp = whs + (size_t)(k0 + k) * 16 + c_grp * 4;
            ulonglong2 w01 = *(const ulonglong2*)wp;
            ulonglong2 w23 = *(const ulonglong2*)(wp + 2);
            acc[0] = ffma2(a0, w01.x, acc[0]);
            acc[1] = ffma2(a1, w01.x, acc[1]);
            acc[2] = ffma2(a0, w01.y, acc[2]);
            acc[3] = ffma2(a1, w01.y, acc[3]);
            acc[4] = ffma2(a0, w23.x, acc[4]);
            acc[5] = ffma2(a1, w23.x, acc[5]);
            acc[6] = ffma2(a0, w23.y, acc[6]);
            acc[7] = ffma2(a1, w23.y, acc[7]);
        }

        // Store packed partials: red[w][cl][bp], bp = b_grp*2 (+1).
        #pragma unroll
        for (int j = 0; j < 4; j++) {
            ulonglong2 v;
            v.x = acc[j * 2];
            v.y = acc[j * 2 + 1];
            *(ulonglong2*)&red[wrp * 288 + (c_grp * 4 + j) * 18 + b_grp * 2] = v;
        }
        __syncthreads();

        // Parallel packed reduce (256 threads, one (cl, bp) each) + xp add.
        if (tid < 256) {
            int g = cl_r >> 2, hu = cl_r & 3;
            float2 xv = __ldcg((const float2*)&g_xp[
                ((size_t)t * C4 + (size_t)(g * 512 + cta * 4 + hu)) * 32 + bp_r * 2]);
            ull v[16];
            #pragma unroll
            for (int w = 0; w < 16; w++)
                v[w] = red[w * 288 + cl_r * 18 + bp_r];
            #pragma unroll
            for (int st = 8; st >= 1; st >>= 1)
                #pragma unroll
                for (int w = 0; w < st; w++) v[w] = fadd2(v[w], v[w + st]);
            sgu[cl_r * 16 + bp_r] = fadd2(v[0], pack2(xv.x, xv.y));
        }
        __syncthreads();

        // Gates: warp hu_g handles col = cta*4 + hu_g, lane = b.
        if (tid < 128) {
            float s0 = sgf[(0 * 4 + hu_g) * 32 + b_g];
            float s1 = sgf[(1 * 4 + hu_g) * 32 + b_g];
            float s2 = sgf[(2 * 4 + hu_g) * 32 + b_g];
            float s3 = sgf[(3 * 4 + hu_g) * 32 + b_g];
            float ig = sigf(s0);
            float fg = sigf(s1);
            float gg = tanhf_fast(s2);
            float og = sigf(s3);
            c_state = fg * c_state + ig * gg;
            float hval = og * tanhf_fast(c_state);

            int col = cta * 4 + hu_g;
            __stcg(&((float*)g_h[pin ^ 1])[col * 32 + b_g], hval);  // coalesced per warp
            ost[b_g * 4 + hu_g] = hval;
        }
        __syncthreads();     // h stores done CTA-wide

        if (t < TSTEPS - 1) {
            if (tid == 0) {
                unsigned old;
                asm volatile("atom.acq_rel.gpu.global.add.u32 %0, [%1], 1;"
                             : "=r"(old) : "l"(grpp) : "memory");
                if (old == 16u * (unsigned)(t + 1) - 1u) {
                    asm volatile("red.release.gpu.global.add.u32 [%0], 1;"
                                 :: "l"(rootp) : "memory");
                }
            }
            // out store overlaps other CTAs' arrivals.
            if (tid >= 128 && tid < 160) {
                int b = tid - 128;
                float4 o4 = *(const float4*)&ost[b * 4];
                *(float4*)&out[(size_t)t * (BATCH * HDIM) + (size_t)b * HDIM + cta * 4] = o4;
            }
            if (tid == 0) {
                unsigned target = 8u * (unsigned)(t + 1);
                unsigned v;
                do {
                    asm volatile("ld.acquire.gpu.global.u32 %0, [%1];"
                                 : "=r"(v) : "l"(rootp) : "memory");
                } while (v < target);
            }
            __syncthreads();
        } else {
            if (tid >= 128 && tid < 160) {
                int b = tid - 128;
                float4 o4 = *(const float4*)&ost[b * 4];
                *(float4*)&out[(size_t)t * (BATCH * HDIM) + (size_t)b * HDIM + cta * 4] = o4;
            }
        }
    }
}

// ---------------------------------------------------------------------------
extern "C" void kernel_launch(void* const* d_in, const int* in_sizes, int n_in,
                              void* d_out, int out_size) {
    const float* emb = (const float*)d_in[0];
    const float* wxi = (const float*)d_in[1];
    const float* whi = (const float*)d_in[2];
    const float* bi  = (const float*)d_in[3];
    const float* wxf = (const float*)d_in[4];
    const float* whf = (const float*)d_in[5];
    const float* bf  = (const float*)d_in[6];
    const float* wxg = (const float*)d_in[7];
    const float* whg = (const float*)d_in[8];
    const float* bg  = (const float*)d_in[9];
    const float* wxo = (const float*)d_in[10];
    const float* who = (const float*)d_in[11];
    const float* bo  = (const float*)d_in[12];
    float* out = (float*)d_out;

    cudaFuncSetAttribute(k_transp, cudaFuncAttributeMaxDynamicSharedMemorySize, 66048);
    cudaFuncSetAttribute(k_xproj,  cudaFuncAttributeMaxDynamicSharedMemorySize, 66560);
    cudaFuncSetAttribute(k_rec,    cudaFuncAttributeMaxDynamicSharedMemorySize, 104960);

    k_transp<<<TSTEPS, 256, 66048>>>(emb);
    k_xproj<<<dim3(16, TSTEPS), 256, 66560>>>(wxi, wxf, wxg, wxo, bi, bf, bg, bo);
    k_init<<<128, 256>>>();
    k_rec<<<NCTA, 512, 104960>>>(whi, whf, whg, who, out);
}

// round 10
// speedup vs baseline: 1.0484x; 1.0484x over previous
#include <cuda_runtime.h>
#include <cstdint>

#define TSTEPS 2048
#define BATCH  32
#define EDIM   512
#define HDIM   512
#define C4     2048
#define NCTA   128

typedef unsigned long long ull;

__device__ float    g_xp[(size_t)TSTEPS * C4 * BATCH];     // [t][c][b]
__device__ float    g_embT[(size_t)TSTEPS * EDIM * BATCH]; // [t][k][b]
__device__ float    g_h[2][HDIM * BATCH];                  // [col][b]
__device__ unsigned g_grp[8];
__device__ unsigned g_root;

__device__ __forceinline__ ull ffma2(ull a, ull b, ull c) {
    ull d;
    asm("fma.rn.f32x2 %0, %1, %2, %3;" : "=l"(d) : "l"(a), "l"(b), "l"(c));
    return d;
}
__device__ __forceinline__ ull fadd2(ull a, ull b) {
    ull d;
    asm("add.rn.f32x2 %0, %1, %2;" : "=l"(d) : "l"(a), "l"(b));
    return d;
}
__device__ __forceinline__ ull pack2(float lo, float hi) {
    return ((ull)__float_as_uint(hi) << 32) | (ull)__float_as_uint(lo);
}
__device__ __forceinline__ float sigf(float x) { return 1.0f / (1.0f + __expf(-x)); }
__device__ __forceinline__ float tanhf_fast(float x) {
    return __fmaf_rn(2.0f, sigf(2.0f * x), -1.0f);
}

// ---------------------------------------------------------------------------
__global__ void k_init() {
    int i = blockIdx.x * blockDim.x + threadIdx.x;
    if (i < 2 * HDIM * BATCH) ((float*)g_h)[i] = 0.0f;
    if (i < 8) g_grp[i] = 0u;
    if (i == 8) g_root = 0u;
}

// ---------------------------------------------------------------------------
// Transpose emb[t][b][k] -> g_embT[t][k][b]. One CTA per t.
// ---------------------------------------------------------------------------
__global__ void __launch_bounds__(256) k_transp(const float* __restrict__ emb) {
    extern __shared__ float tile[];       // [32 b][516] padded
    const int tid = threadIdx.x;
    const int t   = blockIdx.x;
    const float4* src = (const float4*)(emb + (size_t)t * (BATCH * EDIM));
    #pragma unroll
    for (int j = 0; j < 16; j++) {
        int fidx = j * 256 + tid;
        int b  = fidx >> 7;
        int kq = fidx & 127;
        float4 v = src[b * 128 + kq];
        *(float4*)&tile[b * 516 + kq * 4] = v;
    }
    __syncthreads();
    float* dst = g_embT + (size_t)t * (EDIM * BATCH);
    #pragma unroll
    for (int j = 0; j < 16; j++) {
        int oidx = j * 256 + tid;
        int k  = oidx >> 3;
        int bq = oidx & 7;
        float4 v;
        v.x = tile[(bq * 4 + 0) * 516 + k];
        v.y = tile[(bq * 4 + 1) * 516 + k];
        v.z = tile[(bq * 4 + 2) * 516 + k];
        v.w = tile[(bq * 4 + 3) * 516 + k];
        *(float4*)&dst[k * 32 + bq * 4] = v;
    }
}

// ---------------------------------------------------------------------------
// Phase 1 (unchanged from R8): xp = embT @ Wx + b, outer-product 4b x 4c.
// ---------------------------------------------------------------------------
__global__ void __launch_bounds__(256, 2) k_xproj(
    const float* __restrict__ wxi, const float* __restrict__ wxf,
    const float* __restrict__ wxg, const float* __restrict__ wxo,
    const float* __restrict__ bi,  const float* __restrict__ bf,
    const float* __restrict__ bg,  const float* __restrict__ bo)
{
    extern __shared__ ull sx[];          // 2 bufs x [32 k][130] dup'd ull

    const int tid  = threadIdx.x;
    const int lane = tid & 31;
    const int wrp  = tid >> 5;
    const int t    = blockIdx.y;
    const int ct   = blockIdx.x;
    const int gate = ct >> 2;
    const int co   = (ct & 3) * 128;

    const float* W  = (gate == 0) ? wxi : (gate == 1) ? wxf : (gate == 2) ? wxg : wxo;
    const float* bs = (gate == 0) ? bi  : (gate == 1) ? bf  : (gate == 2) ? bg  : bo;

    const int b_grp = lane >> 2;
    const int c_grp = lane & 3;

    float4 pre[4];
    auto load_chunk = [&](int kc) {
        #pragma unroll
        for (int j = 0; j < 4; j++) {
            int idx = j * 256 + tid;
            int kk  = (idx & 7) | ((idx >> 8) << 3);
            int c4  = (idx >> 3) & 31;
            pre[j] = *(const float4*)&W[(size_t)(kc * 32 + kk) * HDIM + co + c4 * 4];
        }
    };
    auto store_chunk = [&](ull* buf) {
        #pragma unroll
        for (int j = 0; j < 4; j++) {
            int idx = j * 256 + tid;
            int kk  = (idx & 7) | ((idx >> 8) << 3);
            int c4  = (idx >> 3) & 31;
            ull* d = buf + kk * 130 + c4 * 4;
            *(ulonglong2*)d       = make_ulonglong2(pack2(pre[j].x, pre[j].x),
                                                    pack2(pre[j].y, pre[j].y));
            *(ulonglong2*)(d + 2) = make_ulonglong2(pack2(pre[j].z, pre[j].z),
                                                    pack2(pre[j].w, pre[j].w));
        }
    };

    const float* At = g_embT + (size_t)t * (EDIM * BATCH);

    ull acc[8];
    #pragma unroll
    for (int j = 0; j < 8; j++) acc[j] = 0ull;

    load_chunk(0);
    store_chunk(sx);
    __syncthreads();

    int p = 0;
    for (int kc = 0; kc < 16; kc++) {
        if (kc < 15) load_chunk(kc + 1);
        const ull*   wb = sx + p * 4160;
        const float* Ab = At + (size_t)(kc * 32) * 32 + b_grp * 4;
        #pragma unroll 8
        for (int k = 0; k < 32; k++) {
            ull a0, a1;
            asm("ld.global.nc.v2.u64 {%0,%1}, [%2];"
                : "=l"(a0), "=l"(a1) : "l"(Ab + k * 32));
            const ull* wp = wb + k * 130 + wrp * 16 + c_grp * 4;
            ulonglong2 w01 = *(const ulonglong2*)wp;
            ulonglong2 w23 = *(const ulonglong2*)(wp + 2);
            acc[0] = ffma2(a0, w01.x, acc[0]);
            acc[1] = ffma2(a1, w01.x, acc[1]);
            acc[2] = ffma2(a0, w01.y, acc[2]);
            acc[3] = ffma2(a1, w01.y, acc[3]);
            acc[4] = ffma2(a0, w23.x, acc[4]);
            acc[5] = ffma2(a1, w23.x, acc[5]);
            acc[6] = ffma2(a0, w23.y, acc[6]);
            acc[7] = ffma2(a1, w23.y, acc[7]);
        }
        if (kc < 15) store_chunk(sx + (p ^ 1) * 4160);
        __syncthreads();
        p ^= 1;
    }

    float* xp = g_xp + ((size_t)t * C4 + (size_t)gate * 512 + co) * 32;
    #pragma unroll
    for (int j = 0; j < 4; j++) {
        int c = wrp * 16 + c_grp * 4 + j;
        float bv = __ldg(&bs[co + c]);
        ull bd = pack2(bv, bv);
        ulonglong2 o;
        o.x = fadd2(acc[j * 2],     bd);
        o.y = fadd2(acc[j * 2 + 1], bd);
        *(ulonglong2*)&xp[(size_t)c * 32 + b_grp * 4] = o;
    }
}

// ---------------------------------------------------------------------------
// Phase 2: persistent recurrence. Outer-product microkernel with software-
// pipelined h loads (8-k chunks, prefetch distance 1, MLP 16 up front).
// ---------------------------------------------------------------------------
#define LOADC(kc, A0, A1)                                                  \
    _Pragma("unroll")                                                      \
    for (int k = 0; k < 8; k++) {                                          \
        asm("ld.global.cg.v2.u64 {%0,%1}, [%2];"                           \
            : "=l"(A0[k]), "=l"(A1[k])                                     \
            : "l"(hb + ((kc) * 8 + k) * 32));                              \
    }

#define COMPC(kc, A0, A1)                                                  \
    _Pragma("unroll")                                                      \
    for (int k = 0; k < 8; k++) {                                          \
        const ull* wp = whs + (size_t)(k0 + (kc) * 8 + k) * 16 + c_grp * 4;\
        ulonglong2 w01 = *(const ulonglong2*)wp;                           \
        ulonglong2 w23 = *(const ulonglong2*)(wp + 2);                     \
        acc[0] = ffma2(A0[k], w01.x, acc[0]);                              \
        acc[1] = ffma2(A1[k], w01.x, acc[1]);                              \
        acc[2] = ffma2(A0[k], w01.y, acc[2]);                              \
        acc[3] = ffma2(A1[k], w01.y, acc[3]);                              \
        acc[4] = ffma2(A0[k], w23.x, acc[4]);                              \
        acc[5] = ffma2(A1[k], w23.x, acc[5]);                              \
        acc[6] = ffma2(A0[k], w23.y, acc[6]);                              \
        acc[7] = ffma2(A1[k], w23.y, acc[7]);                              \
    }

__global__ void __launch_bounds__(512, 1) k_rec(
    const float* __restrict__ whi, const float* __restrict__ whf,
    const float* __restrict__ whg, const float* __restrict__ who,
    float* __restrict__ out)
{
    extern __shared__ ull sr[];
    ull*   whs = sr;                     // [512 k][16 lc] dup'd      (8192 ull)
    ull*   red = sr + 8192;              // [16 w][16 c x 18]         (4608 ull)
    ull*   sgu = sr + 12800;             // [16 c][16 bp]             (256 ull)
    float* sgf = (float*)sgu;
    float* ost = (float*)(sr + 13056);   // [32 b][4 hu]              (64 ull)

    const int tid  = threadIdx.x;
    const int lane = tid & 31;
    const int wrp  = tid >> 5;           // 0..15
    const int cta  = blockIdx.x;

    for (int i = tid; i < 8192; i += 512) {
        int k = i >> 4, lc = i & 15;
        int g = lc >> 2, hu = lc & 3;
        const float* Wp = (g == 0) ? whi : (g == 1) ? whf : (g == 2) ? whg : who;
        float w = Wp[(size_t)k * HDIM + cta * 4 + hu];
        whs[i] = pack2(w, w);
    }
    __syncthreads();

    const int b_grp = lane >> 2;
    const int c_grp = lane & 3;
    const int k0    = wrp * 32;
    const int hu_g  = tid >> 5;          // gate phase (tid<128)
    const int b_g   = tid & 31;
    const int cl_r  = tid >> 4;          // reduce phase (tid<256)
    const int bp_r  = tid & 15;
    float c_state = 0.0f;

    unsigned* grpp  = &g_grp[cta >> 4];
    unsigned* rootp = &g_root;

    for (int t = 0; t < TSTEPS; t++) {
        const int pin = t & 1;
        const float* hb = g_h[pin] + k0 * 32 + b_grp * 4;

        // xp prefetch (consumed in the reduce phase, ~2K cycles later).
        float2 xv = make_float2(0.f, 0.f);
        if (tid < 256) {
            int g = cl_r >> 2, hu = cl_r & 3;
            xv = __ldcg((const float2*)&g_xp[
                ((size_t)t * C4 + (size_t)(g * 512 + cta * 4 + hu)) * 32 + bp_r * 2]);
        }

        ull acc[8];
        #pragma unroll
        for (int j = 0; j < 8; j++) acc[j] = 0ull;

        // Software-pipelined matmul: chunks of 8 k, distance-1 prefetch.
        {
            ull pa0[8], pa1[8], pb0[8], pb1[8];
            LOADC(0, pa0, pa1);
            LOADC(1, pb0, pb1);
            COMPC(0, pa0, pa1);
            LOADC(2, pa0, pa1);
            COMPC(1, pb0, pb1);
            LOADC(3, pb0, pb1);
            COMPC(2, pa0, pa1);
            COMPC(3, pb0, pb1);
        }

        #pragma unroll
        for (int j = 0; j < 4; j++) {
            ulonglong2 v;
            v.x = acc[j * 2];
            v.y = acc[j * 2 + 1];
            *(ulonglong2*)&red[wrp * 288 + (c_grp * 4 + j) * 18 + b_grp * 2] = v;
        }
        __syncthreads();

        // Parallel packed reduce: 256 threads, one (lc, b-pair) each.
        if (tid < 256) {
            ull v[16];
            #pragma unroll
            for (int w = 0; w < 16; w++)
                v[w] = red[w * 288 + cl_r * 18 + bp_r];
            #pragma unroll
            for (int st = 8; st >= 1; st >>= 1)
                #pragma unroll
                for (int w = 0; w < st; w++) v[w] = fadd2(v[w], v[w + st]);
            sgu[cl_r * 16 + bp_r] = fadd2(v[0], pack2(xv.x, xv.y));
        }
        __syncthreads();

        if (tid < 128) {
            float s0 = sgf[(0 * 4 + hu_g) * 32 + b_g];
            float s1 = sgf[(1 * 4 + hu_g) * 32 + b_g];
            float s2 = sgf[(2 * 4 + hu_g) * 32 + b_g];
            float s3 = sgf[(3 * 4 + hu_g) * 32 + b_g];
            float ig = sigf(s0);
            float fg = sigf(s1);
            float gg = tanhf_fast(s2);
            float og = sigf(s3);
            c_state = fg * c_state + ig * gg;
            float hval = og * tanhf_fast(c_state);

            int col = cta * 4 + hu_g;
            __stcg(&((float*)g_h[pin ^ 1])[col * 32 + b_g], hval);
            ost[b_g * 4 + hu_g] = hval;
        }
        __syncthreads();

        if (t < TSTEPS - 1) {
            if (tid == 0) {
                unsigned old;
                asm volatile("atom.acq_rel.gpu.global.add.u32 %0, [%1], 1;"
                             : "=r"(old) : "l"(grpp) : "memory");
                if (old == 16u * (unsigned)(t + 1) - 1u) {
                    asm volatile("red.release.gpu.global.add.u32 [%0], 1;"
                                 :: "l"(rootp) : "memory");
                }
            }
            if (tid >= 128 && tid < 160) {
                int b = tid - 128;
                float4 o4 = *(const float4*)&ost[b * 4];
                *(float4*)&out[(size_t)t * (BATCH * HDIM) + (size_t)b * HDIM + cta * 4] = o4;
            }
            if (tid == 0) {
                unsigned target = 8u * (unsigned)(t + 1);
                unsigned v;
                do {
                    asm volatile("ld.acquire.gpu.global.u32 %0, [%1];"
                                 : "=r"(v) : "l"(rootp) : "memory");
                } while (v < target);
            }
            __syncthreads();
        } else {
            if (tid >= 128 && tid < 160) {
                int b = tid - 128;
                float4 o4 = *(const float4*)&ost[b * 4];
                *(float4*)&out[(size_t)t * (BATCH * HDIM) + (size_t)b * HDIM + cta * 4] = o4;
            }
        }
    }
}

// ---------------------------------------------------------------------------
extern "C" void kernel_launch(void* const* d_in, const int* in_sizes, int n_in,
                              void* d_out, int out_size) {
    const float* emb = (const float*)d_in[0];
    const float* wxi = (const float*)d_in[1];
    const float* whi = (const float*)d_in[2];
    const float* bi  = (const float*)d_in[3];
    const float* wxf = (const float*)d_in[4];
    const float* whf = (const float*)d_in[5];
    const float* bf  = (const float*)d_in[6];
    const float* wxg = (const float*)d_in[7];
    const float* whg = (const float*)d_in[8];
    const float* bg  = (const float*)d_in[9];
    const float* wxo = (const float*)d_in[10];
    const float* who = (const float*)d_in[11];
    const float* bo  = (const float*)d_in[12];
    float* out = (float*)d_out;

    cudaFuncSetAttribute(k_transp, cudaFuncAttributeMaxDynamicSharedMemorySize, 66048);
    cudaFuncSetAttribute(k_xproj,  cudaFuncAttributeMaxDynamicSharedMemorySize, 66560);
    cudaFuncSetAttribute(k_rec,    cudaFuncAttributeMaxDynamicSharedMemorySize, 104960);

    k_transp<<<TSTEPS, 256, 66048>>>(emb);
    k_xproj<<<dim3(16, TSTEPS), 256, 66560>>>(wxi, wxf, wxg, wxo, bi, bf, bg, bo);
    k_init<<<128, 256>>>();
    k_rec<<<NCTA, 512, 104960>>>(whi, whf, whg, who, out);
}